// round 5
// baseline (speedup 1.0000x reference)
#include <cuda_runtime.h>

#define MROWS 64000
#define MAXD  160

// ---------------- scratch (device globals: no allocation allowed) ----------------
__device__ float g_atlas0[MROWS * MAXD];
__device__ float g_atlas1[MROWS * MAXD];
__device__ float g_B    [MROWS * MAXD];
__device__ float g_q    [MROWS * MAXD];
__device__ float g_k    [MROWS * MAXD];
__device__ float g_v    [MROWS * MAXD];
__device__ float g_cross[MROWS * MAXD];
__device__ float g_Spart[64 * MAXD * MAXD];
__device__ float g_S    [MAXD * MAXD];
__device__ float g_attnT[MAXD * MAXD];

// ---------------- pad + unfold: feat -> (64000, d) ----------------
__global__ __launch_bounds__(256) void unfold_kernel(
    const float* __restrict__ src, float* __restrict__ dst, int d,
    int D0, int D1, int D2, long s0, long s1, long s2, long sc,
    int w0, int w1, int w2, int pb0, int pb1, int pb2)
{
    long idx = (long)blockIdx.x * blockDim.x + threadIdx.x;
    long total = (long)MROWS * d;
    if (idx >= total) return;
    int  s = (int)(idx % d);
    long m = idx / d;
    int c = (int)(m / 1000);
    int r = (int)(m % 1000);
    int i0 = r / 100, i1 = (r / 10) % 10, i2 = r % 10;
    int z2 = s % w2; int t = s / w2; int z1 = t % w1; int z0 = t / w1;
    int p0 = i0 * w0 + z0 - pb0;
    int p1 = i1 * w1 + z1 - pb1;
    int p2 = i2 * w2 + z2 - pb2;
    float v = 0.f;
    if ((unsigned)p0 < (unsigned)D0 && (unsigned)p1 < (unsigned)D1 && (unsigned)p2 < (unsigned)D2)
        v = src[(long)c * sc + (long)p0 * s0 + (long)p1 * s1 + (long)p2 * s2];
    dst[idx] = v;
}

// ---------------- fold: (64000, d) -> output tensor (crop + strides) ----------------
__global__ __launch_bounds__(256) void fold_kernel(
    const float* __restrict__ cross, float* __restrict__ out, int d,
    int D0, int D1, int D2, long s0, long s1, long s2, long sc,
    int w0, int w1, int w2, int pb0, int pb1, int pb2)
{
    long idx = (long)blockIdx.x * blockDim.x + threadIdx.x;
    long total = 64L * D0 * D1 * D2;
    if (idx >= total) return;
    int x2 = (int)(idx % D2); long t = idx / D2;
    int x1 = (int)(t % D1);  t /= D1;
    int x0 = (int)(t % D0);
    int c  = (int)(t / D0);
    int p0 = x0 + pb0, p1 = x1 + pb1, p2 = x2 + pb2;
    int i0 = p0 / w0, z0 = p0 - i0 * w0;
    int i1 = p1 / w1, z1 = p1 - i1 * w1;
    int i2 = p2 / w2, z2 = p2 - i2 * w2;
    long m = (long)c * 1000 + i0 * 100 + i1 * 10 + i2;
    int  s = (z0 * w1 + z1) * w2 + z2;
    out[(long)c * sc + (long)x0 * s0 + (long)x1 * s1 + (long)x2 * s2] = cross[m * d + s];
}

// ---------------- nearest3d resample of atlas cube ----------------
__global__ __launch_bounds__(256) void resample_kernel(
    const float* __restrict__ src, float* __restrict__ dst,
    int wp0, int wp1, int wp2, int wn0, int wn1, int wn2)
{
    int dp = wp0 * wp1 * wp2, dn = wn0 * wn1 * wn2;
    long idx = (long)blockIdx.x * blockDim.x + threadIdx.x;
    long total = (long)MROWS * dn;
    if (idx >= total) return;
    int  s = (int)(idx % dn);
    long m = idx / dn;
    int z2 = s % wn2; int t = s / wn2; int z1 = t % wn1; int z0 = t / wn1;
    int o0 = (z0 * wp0) / wn0;
    int o1 = (z1 * wp1) / wn1;
    int o2 = (z2 * wp2) / wn2;
    dst[idx] = src[m * dp + (o0 * wp1 + o1) * wp2 + o2];
}

// ---------------- fp32 SGEMM  C[M,N] = A[M,K] @ W[K,N] (+ bias) ----------------
// BM=128, BN=40, BK=16, 256 threads, 4x5 microtile (32 row-groups x 8 col-groups).
// Double-buffered smem; one __syncthreads per K-step; LDG issued before compute.
#define BM 128
#define BN 40
#define BKK 16
#define AST 132   // As inner stride (floats): mult of 4 for LDS.128 alignment, padded vs 128

__global__ __launch_bounds__(256, 3) void sgemm_bias(
    const float* __restrict__ A, const float* __restrict__ W,
    const float* __restrict__ bias, float* __restrict__ C,
    int M, int K, int N)
{
    __shared__ float As[2][BKK][AST];
    __shared__ float Ws[2][BKK][BN];
    const int bm = blockIdx.x * BM;
    const int bn = blockIdx.y * BN;
    const int tid = threadIdx.x;
    const int tx = tid & 7;      // 8 col groups of 5
    const int ty = tid >> 3;     // 32 row groups of 4

    // A loader: l = i*256+tid -> m = l>>2 (0..127), k-quad = (l&3)*4
    const int am = tid >> 2;          // i=0 gives m=am, i=1 gives m=am+64
    const int kq = (tid & 3) * 4;
    const long r0 = (long)(bm + am) * K;
    const long r1 = (long)(bm + am + 64) * K;

    const int T = (K + BKK - 1) / BKK;

    float acc[4][5];
#pragma unroll
    for (int i = 0; i < 4; i++)
#pragma unroll
        for (int j = 0; j < 5; j++) acc[i][j] = 0.f;

    float4 pa0, pa1;
    float  pw[3];

    // ---- prologue: tile 0 ----
    {
        const int kb = kq;  // k0 = 0
        if (kb + 3 < K) {
            pa0 = *(const float4*)&A[r0 + kb];
            pa1 = *(const float4*)&A[r1 + kb];
        } else {
            pa0.x = (kb     < K) ? A[r0 + kb    ] : 0.f;
            pa0.y = (kb + 1 < K) ? A[r0 + kb + 1] : 0.f;
            pa0.z = (kb + 2 < K) ? A[r0 + kb + 2] : 0.f;
            pa0.w = (kb + 3 < K) ? A[r0 + kb + 3] : 0.f;
            pa1.x = (kb     < K) ? A[r1 + kb    ] : 0.f;
            pa1.y = (kb + 1 < K) ? A[r1 + kb + 1] : 0.f;
            pa1.z = (kb + 2 < K) ? A[r1 + kb + 2] : 0.f;
            pa1.w = (kb + 3 < K) ? A[r1 + kb + 3] : 0.f;
        }
#pragma unroll
        for (int j = 0; j < 3; j++) {
            int l = j * 256 + tid;
            float v = 0.f;
            if (l < BKK * BN) {
                int k = l / BN, n = l - k * BN;
                if (k < K && bn + n < N) v = W[(long)k * N + bn + n];
            }
            pw[j] = v;
        }
        As[0][kq    ][am] = pa0.x;  As[0][kq + 1][am] = pa0.y;
        As[0][kq + 2][am] = pa0.z;  As[0][kq + 3][am] = pa0.w;
        As[0][kq    ][am + 64] = pa1.x;  As[0][kq + 1][am + 64] = pa1.y;
        As[0][kq + 2][am + 64] = pa1.z;  As[0][kq + 3][am + 64] = pa1.w;
#pragma unroll
        for (int j = 0; j < 3; j++) {
            int l = j * 256 + tid;
            if (l < BKK * BN) { int k = l / BN, n = l - k * BN; Ws[0][k][n] = pw[j]; }
        }
    }
    __syncthreads();

    for (int t = 0; t < T; t++) {
        const int cur = t & 1;
        const bool more = (t + 1 < T);
        if (more) {
            const int k0 = (t + 1) * BKK;
            const int kb = k0 + kq;
            if (kb + 3 < K) {
                pa0 = *(const float4*)&A[r0 + kb];
                pa1 = *(const float4*)&A[r1 + kb];
            } else {
                pa0.x = (kb     < K) ? A[r0 + kb    ] : 0.f;
                pa0.y = (kb + 1 < K) ? A[r0 + kb + 1] : 0.f;
                pa0.z = (kb + 2 < K) ? A[r0 + kb + 2] : 0.f;
                pa0.w = (kb + 3 < K) ? A[r0 + kb + 3] : 0.f;
                pa1.x = (kb     < K) ? A[r1 + kb    ] : 0.f;
                pa1.y = (kb + 1 < K) ? A[r1 + kb + 1] : 0.f;
                pa1.z = (kb + 2 < K) ? A[r1 + kb + 2] : 0.f;
                pa1.w = (kb + 3 < K) ? A[r1 + kb + 3] : 0.f;
            }
#pragma unroll
            for (int j = 0; j < 3; j++) {
                int l = j * 256 + tid;
                float v = 0.f;
                if (l < BKK * BN) {
                    int k = l / BN, n = l - k * BN;
                    if (k0 + k < K && bn + n < N) v = W[(long)(k0 + k) * N + bn + n];
                }
                pw[j] = v;
            }
        }
        // compute this tile (hides the LDGs above)
#pragma unroll
        for (int kk = 0; kk < BKK; kk++) {
            float4 ra = *(const float4*)&As[cur][kk][ty * 4];
            float rw[5];
#pragma unroll
            for (int j = 0; j < 5; j++) rw[j] = Ws[cur][kk][tx * 5 + j];
#pragma unroll
            for (int j = 0; j < 5; j++) {
                acc[0][j] += ra.x * rw[j];
                acc[1][j] += ra.y * rw[j];
                acc[2][j] += ra.z * rw[j];
                acc[3][j] += ra.w * rw[j];
            }
        }
        if (more) {
            const int nxt = cur ^ 1;
            As[nxt][kq    ][am] = pa0.x;  As[nxt][kq + 1][am] = pa0.y;
            As[nxt][kq + 2][am] = pa0.z;  As[nxt][kq + 3][am] = pa0.w;
            As[nxt][kq    ][am + 64] = pa1.x;  As[nxt][kq + 1][am + 64] = pa1.y;
            As[nxt][kq + 2][am + 64] = pa1.z;  As[nxt][kq + 3][am + 64] = pa1.w;
#pragma unroll
            for (int j = 0; j < 3; j++) {
                int l = j * 256 + tid;
                if (l < BKK * BN) { int k = l / BN, n = l - k * BN; Ws[nxt][k][n] = pw[j]; }
            }
        }
        __syncthreads();
    }

    // epilogue
#pragma unroll
    for (int i = 0; i < 4; i++) {
        const long m = bm + ty * 4 + i;
#pragma unroll
        for (int j = 0; j < 5; j++) {
            int n = bn + tx * 5 + j;
            if (n < N) {
                float v = acc[i][j];
                if (bias) v += bias[n];
                C[m * N + n] = v;
            }
        }
    }
}

// ---------------- S partials: Sp[cz][i][j] = sum_{m in chunk cz} q[m,i]*k[m,j] ----------------
// 32 chunks of 2000 rows; 64x64 tile, 4x4 micro, double-buffered, float4 smem frags.
#define SB 64
#define SMB 16
#define NCH 32
#define CHM 2000
#define QST 68

__global__ __launch_bounds__(256, 3) void spart_kernel(
    const float* __restrict__ q, const float* __restrict__ k,
    float* __restrict__ Sp, int N)
{
    __shared__ float Qs[2][SMB][QST];
    __shared__ float Ks[2][SMB][QST];
    const int i0 = blockIdx.x * SB;
    const int j0 = blockIdx.y * SB;
    const int cz = blockIdx.z;
    const int m0 = cz * CHM;
    const int tid = threadIdx.x;
    const int tx = tid & 15;
    const int ty = tid >> 4;

    // loader: 16x64 floats = 256 float4: mm = tid>>4, cb = (tid&15)*4
    const int mm = tid >> 4;
    const int cb = (tid & 15) * 4;
    const int qcol = i0 + cb;   // N%4==0 so (qcol<N) => full float4 in-row
    const int kcol = j0 + cb;

    const int T = CHM / SMB;   // 125

    float acc[4][4];
#pragma unroll
    for (int i = 0; i < 4; i++)
#pragma unroll
        for (int j = 0; j < 4; j++) acc[i][j] = 0.f;

    float4 pq, pk;
    const float4 z4 = make_float4(0.f, 0.f, 0.f, 0.f);

    // prologue
    {
        long gm = m0 + mm;
        pq = (qcol < N) ? *(const float4*)&q[gm * N + qcol] : z4;
        pk = (kcol < N) ? *(const float4*)&k[gm * N + kcol] : z4;
        *(float4*)&Qs[0][mm][cb] = pq;
        *(float4*)&Ks[0][mm][cb] = pk;
    }
    __syncthreads();

    for (int t = 0; t < T; t++) {
        const int cur = t & 1;
        const bool more = (t + 1 < T);
        if (more) {
            long gm = m0 + (t + 1) * SMB + mm;
            pq = (qcol < N) ? *(const float4*)&q[gm * N + qcol] : z4;
            pk = (kcol < N) ? *(const float4*)&k[gm * N + kcol] : z4;
        }
#pragma unroll
        for (int kk = 0; kk < SMB; kk++) {
            float4 rq = *(const float4*)&Qs[cur][kk][ty * 4];
            float4 rk = *(const float4*)&Ks[cur][kk][tx * 4];
            acc[0][0] += rq.x * rk.x; acc[0][1] += rq.x * rk.y;
            acc[0][2] += rq.x * rk.z; acc[0][3] += rq.x * rk.w;
            acc[1][0] += rq.y * rk.x; acc[1][1] += rq.y * rk.y;
            acc[1][2] += rq.y * rk.z; acc[1][3] += rq.y * rk.w;
            acc[2][0] += rq.z * rk.x; acc[2][1] += rq.z * rk.y;
            acc[2][2] += rq.z * rk.z; acc[2][3] += rq.z * rk.w;
            acc[3][0] += rq.w * rk.x; acc[3][1] += rq.w * rk.y;
            acc[3][2] += rq.w * rk.z; acc[3][3] += rq.w * rk.w;
        }
        if (more) {
            const int nxt = cur ^ 1;
            *(float4*)&Qs[nxt][mm][cb] = pq;
            *(float4*)&Ks[nxt][mm][cb] = pk;
        }
        __syncthreads();
    }

#pragma unroll
    for (int i = 0; i < 4; i++) {
        int gi = i0 + ty * 4 + i;
#pragma unroll
        for (int j = 0; j < 4; j++) {
            int gj = j0 + tx * 4 + j;
            if (gi < N && gj < N)
                Sp[(long)cz * N * N + (long)gi * N + gj] = acc[i][j];
        }
    }
}

__global__ __launch_bounds__(256) void sreduce_kernel(
    const float* __restrict__ Sp, float* __restrict__ S, int NN)
{
    int idx = blockIdx.x * blockDim.x + threadIdx.x;
    if (idx >= NN) return;
    float s = 0.f;
#pragma unroll 4
    for (int c = 0; c < NCH; c++) s += Sp[(long)c * NN + idx];
    S[idx] = s;
}

// softmax over j of S[i,:], written TRANSPOSED: attnT[j,i]
__global__ __launch_bounds__(256) void softmaxT_kernel(
    const float* __restrict__ S, float* __restrict__ attnT, int N)
{
    __shared__ float red[256];
    const int i = blockIdx.x;
    const int tid = threadIdx.x;
    float v = (tid < N) ? S[(long)i * N + tid] : -3.4e38f;
    red[tid] = v; __syncthreads();
    for (int off = 128; off > 0; off >>= 1) {
        if (tid < off) red[tid] = fmaxf(red[tid], red[tid + off]);
        __syncthreads();
    }
    float mx = red[0]; __syncthreads();
    float e = (tid < N) ? expf(v - mx) : 0.f;
    red[tid] = e; __syncthreads();
    for (int off = 128; off > 0; off >>= 1) {
        if (tid < off) red[tid] += red[tid + off];
        __syncthreads();
    }
    float sum = red[0];
    if (tid < N) attnT[(long)tid * N + i] = e / sum;
}

// ---------------- driver ----------------
struct BranchDesc {
    int D0, D1, D2;
    long s0, s1, s2, sc;
    int w0, w1, w2;
    int pb0, pb1, pb2;
    long outOff;
    int wi;
};

extern "C" void kernel_launch(void* const* d_in, const int* in_sizes, int n_in,
                              void* d_out, int out_size)
{
    const float* axi   = (const float*)d_in[0];
    const float* cor   = (const float*)d_in[1];
    const float* sag   = (const float*)d_in[2];
    const float* atlas = (const float*)d_in[3];
    float* out = (float*)d_out;

    float *A0, *A1, *B, *Q, *Kb, *V, *Cr, *Sp, *S, *AT;
    cudaGetSymbolAddress((void**)&A0, g_atlas0);
    cudaGetSymbolAddress((void**)&A1, g_atlas1);
    cudaGetSymbolAddress((void**)&B,  g_B);
    cudaGetSymbolAddress((void**)&Q,  g_q);
    cudaGetSymbolAddress((void**)&Kb, g_k);
    cudaGetSymbolAddress((void**)&V,  g_v);
    cudaGetSymbolAddress((void**)&Cr, g_cross);
    cudaGetSymbolAddress((void**)&Sp, g_Spart);
    cudaGetSymbolAddress((void**)&S,  g_S);
    cudaGetSymbolAddress((void**)&AT, g_attnT);

    // atlas_feat (64,46,56,38): ps=(50,60,40), w=(5,6,4), pb=(2,2,1)
    {
        long total = (long)MROWS * 120;
        unfold_kernel<<<(unsigned)((total + 255) / 256), 256>>>(
            atlas, A0, 120, 46, 56, 38, 2128, 38, 1, 97888, 5, 6, 4, 2, 2, 1);
    }

    BranchDesc br[3] = {
        { 48, 66, 38, 2508, 38,   1, 120384, 5, 7, 4, 1, 2, 1, 0L,        4 },
        { 38, 38, 66, 2508,  1,  38,  95304, 4, 4, 7, 1, 1, 2, 7704576L, 10 },
        { 38, 78, 48,    1, 38, 2964, 142272, 4, 8, 5, 1, 1, 1, 13804032L, 16 },
    };

    float* Aprev = A0;
    float* Acur  = A1;
    int wp0 = 5, wp1 = 6, wp2 = 4;

    for (int b = 0; b < 3; b++) {
        const BranchDesc& r = br[b];
        const int d = r.w0 * r.w1 * r.w2;
        const float* Wq = (const float*)d_in[r.wi + 0];
        const float* bq = (const float*)d_in[r.wi + 1];
        const float* Wk = (const float*)d_in[r.wi + 2];
        const float* bk = (const float*)d_in[r.wi + 3];
        const float* Wv = (const float*)d_in[r.wi + 4];
        const float* bv = (const float*)d_in[r.wi + 5];

        {
            long total = (long)MROWS * d;
            resample_kernel<<<(unsigned)((total + 255) / 256), 256>>>(
                Aprev, Acur, wp0, wp1, wp2, r.w0, r.w1, r.w2);
        }
        {
            long total = (long)MROWS * d;
            unfold_kernel<<<(unsigned)((total + 255) / 256), 256>>>(
                b == 0 ? axi : (b == 1 ? cor : sag), B, d,
                r.D0, r.D1, r.D2, r.s0, r.s1, r.s2, r.sc,
                r.w0, r.w1, r.w2, r.pb0, r.pb1, r.pb2);
        }
        dim3 gg(MROWS / BM, (d + BN - 1) / BN);
        sgemm_bias<<<gg, 256>>>(Acur, Wq, bq, Q,  MROWS, d, d);
        sgemm_bias<<<gg, 256>>>(B,    Wk, bk, Kb, MROWS, d, d);
        sgemm_bias<<<gg, 256>>>(B,    Wv, bv, V,  MROWS, d, d);

        int tI = (d + SB - 1) / SB;
        dim3 gs(tI, tI, NCH);
        spart_kernel<<<gs, 256>>>(Q, Kb, Sp, d);
        sreduce_kernel<<<(d * d + 255) / 256, 256>>>(Sp, S, d * d);
        softmaxT_kernel<<<d, 256>>>(S, AT, d);

        sgemm_bias<<<gg, 256>>>(V, AT, (const float*)nullptr, Cr, MROWS, d, d);
        {
            long total = 64L * r.D0 * r.D1 * r.D2;
            fold_kernel<<<(unsigned)((total + 255) / 256), 256>>>(
                Cr, out + r.outOff, d,
                r.D0, r.D1, r.D2, r.s0, r.s1, r.s2, r.sc,
                r.w0, r.w1, r.w2, r.pb0, r.pb1, r.pb2);
        }
        float* t = Aprev; Aprev = Acur; Acur = t;
        wp0 = r.w0; wp1 = r.w1; wp2 = r.w2;
    }
}